// round 13
// baseline (speedup 1.0000x reference)
#include <cuda_runtime.h>
#include <cuda_fp16.h>
#include <cstdint>

#define M_TOTAL 2048
#define K_TOTAL 4096
#define N_TOTAL 11008
#define GROUPSZ 128
#define NPACK   (N_TOTAL / 8)   // 1376

// Scratch (__device__ globals: allocation-free rules)
__device__ __half g_W[(size_t)K_TOTAL * N_TOTAL];   // ~90 MB fp16 dequantized W [K][N]
__device__ __half g_X[(size_t)M_TOTAL * K_TOTAL];   // ~16 MB fp16 activations [M][K]

// M*K/8 = 1,048,576 packs of 8; /256 threads = 4096 blocks
#define CONV_NBLK 4096
#define DEQ_NBLK  (K_TOTAL * NPACK / 256)                // 22016

// ---------------------------------------------------------------------------
// Kernel 1 (merged prep): convert x fp32->fp16  +  dequant int4->fp16 [K][N]
// fp16 magic-number dequant (R11-proven, ~30us total).
// ---------------------------------------------------------------------------
__global__ void prep_kernel(const float* __restrict__ x,
                            const int* __restrict__ qweight,
                            const int* __restrict__ qzeros,
                            const float* __restrict__ scales) {
    const int b = blockIdx.x;
    if (b < CONV_NBLK) {
        int idx = b * 256 + threadIdx.x;
        const float4* xv = (const float4*)x;
        float4 f0 = xv[idx * 2 + 0];
        float4 f1 = xv[idx * 2 + 1];
        __half2 h[4];
        h[0] = __floats2half2_rn(f0.x, f0.y);
        h[1] = __floats2half2_rn(f0.z, f0.w);
        h[2] = __floats2half2_rn(f1.x, f1.y);
        h[3] = __floats2half2_rn(f1.z, f1.w);
        *(uint4*)(&g_X[(size_t)idx * 8]) = *(uint4*)h;
    } else {
        int idx = (b - CONV_NBLK) * 256 + threadIdx.x;
        int k  = idx / NPACK;
        int np = idx - k * NPACK;
        int g  = k / GROUPSZ;

        uint32_t qw = ((const uint32_t*)qweight)[idx];
        uint32_t qz = ((const uint32_t*)qzeros)[(size_t)g * NPACK + np];
        const float4* s4 = (const float4*)(scales + (size_t)g * N_TOTAL + np * 8);
        float4 s0 = s4[0];
        float4 s1 = s4[1];
        __half2 sh[4];
        sh[0] = __floats2half2_rn(s0.x, s0.y);
        sh[1] = __floats2half2_rn(s0.z, s0.w);
        sh[2] = __floats2half2_rn(s1.x, s1.y);
        sh[3] = __floats2half2_rn(s1.z, s1.w);

        __half2 r[4];
#pragma unroll
        for (int p = 0; p < 4; p++) {
            uint32_t xw = qw >> (8 * p);
            uint32_t xz = qz >> (8 * p);
            uint32_t tw = 0x64006400u | (xw & 0xFu) | ((xw & 0xF0u) << 12);
            uint32_t tz = 0x64006400u | (xz & 0xFu) | ((xz & 0xF0u) << 12);
            __half2 d = __hsub2(*(__half2*)&tw, *(__half2*)&tz);  // exact ints
            r[p] = __hmul2(d, sh[p]);
        }
        *(uint4*)(&g_W[(size_t)k * N_TOTAL + np * 8]) = *(uint4*)r;
    }
}

// ---------------------------------------------------------------------------
// Kernel 2: GEMM  out[M,N] = X[M,K] * W[K,N] + bias
// mma.sync m16n8k16 fp16->fp32.  BM=128 BN=64 BK=64, 8 warps (4Mx2N),
// warp tile 32x32 -> acc 32 regs/thread.  2-stage cp.async (R1-proven loop),
// OCCUPANCY 3 (launch_bounds(256,3), 24 warps/SM).  Grid swizzled:
// blockIdx.x = bm fastest -> A/B tiles reused from L2 within a wave.
// ---------------------------------------------------------------------------
#define BM 128
#define BN 64
#define BK 64
#define LDA_S 72            // halves per A row (144B -> conflict-free ldsm)
#define LDB_S 72            // halves per B row (144B -> conflict-free ldsm.trans)
#define A_SM_BYTES (BM * LDA_S * 2)            // 18432
#define B_SM_BYTES (BK * LDB_S * 2)            // 9216
#define STAGE_BYTES (A_SM_BYTES + B_SM_BYTES)  // 27648
#define SMEM_TOTAL (2 * STAGE_BYTES)           // 55296 (x3 CTA = 166KB <= 228KB)
#define KT (K_TOTAL / BK)   // 64

__device__ __forceinline__ uint32_t smem_u32(const void* p) {
    return (uint32_t)__cvta_generic_to_shared(p);
}
__device__ __forceinline__ void cp_async_16(uint32_t saddr, const void* gaddr) {
    asm volatile("cp.async.cg.shared.global [%0], [%1], 16;\n" :: "r"(saddr), "l"(gaddr));
}

__global__ void __launch_bounds__(256, 3) gemm_kernel(const float* __restrict__ bias,
                                                      float* __restrict__ out) {
    extern __shared__ char smem[];

    const int tid  = threadIdx.x;
    const int lane = tid & 31;
    const int warp = tid >> 5;
    const int warp_m = warp & 3;   // 0..3 -> 32 rows each
    const int warp_n = warp >> 2;  // 0..1 -> 32 cols each
    const int bm = blockIdx.x;     // M tile (16)  -- fastest
    const int bn = blockIdx.y;     // N tile (172)

    // coalesced global->smem mapping (128B rows, 8 threads per row)
    const int a_row = tid >> 3;          // 0..31 (+32 per iter, 4 iters)
    const int a_c0  = (tid & 7) * 8;
    // B: 64 rows, 2 per thread
    const int b_row = tid >> 3;          // 0..31 (+32, 2 iters)
    const int b_c0  = (tid & 7) * 8;

    const __half* gA = g_X + (size_t)(bm * BM) * K_TOTAL;
    const __half* gB = g_W + (size_t)(bn * BN);

    float acc[2][4][4];
#pragma unroll
    for (int i = 0; i < 2; i++)
#pragma unroll
        for (int j = 0; j < 4; j++)
#pragma unroll
            for (int c = 0; c < 4; c++) acc[i][j][c] = 0.f;

#define LOAD_STAGE(st, kq) do {                                                 \
        const int _k0 = (kq) * BK;                                              \
        __half* _As = (__half*)(smem + (st) * STAGE_BYTES);                     \
        __half* _Bs = (__half*)(smem + (st) * STAGE_BYTES + A_SM_BYTES);        \
        _Pragma("unroll")                                                       \
        for (int _i = 0; _i < 4; _i++) {                                        \
            int _r = a_row + _i * 32;                                           \
            cp_async_16(smem_u32(&_As[_r * LDA_S + a_c0]),                      \
                        gA + (size_t)_r * K_TOTAL + _k0 + a_c0);                \
        }                                                                       \
        _Pragma("unroll")                                                       \
        for (int _i = 0; _i < 2; _i++) {                                        \
            int _r = b_row + _i * 32;                                           \
            cp_async_16(smem_u32(&_Bs[_r * LDB_S + b_c0]),                      \
                        gB + (size_t)(_k0 + _r) * N_TOTAL + b_c0);              \
        }                                                                       \
        asm volatile("cp.async.commit_group;\n" ::);                            \
    } while (0)

    LOAD_STAGE(0, 0);

    int buf = 0;
    for (int kt = 0; kt < KT; kt++) {
        if (kt + 1 < KT) {
            LOAD_STAGE(buf ^ 1, kt + 1);
            asm volatile("cp.async.wait_group 1;\n" ::);
        } else {
            asm volatile("cp.async.wait_group 0;\n" ::);
        }
        __syncthreads();

        const uint32_t a_base = smem_u32(smem + buf * STAGE_BYTES);
        const uint32_t b_base = smem_u32(smem + buf * STAGE_BYTES + A_SM_BYTES);

#pragma unroll
        for (int k16 = 0; k16 < 4; k16++) {
            uint32_t a[2][4];
            uint32_t b[4][2];
#pragma unroll
            for (int mt = 0; mt < 2; mt++) {
                int row = warp_m * 32 + mt * 16 + (lane & 15);
                int col = k16 * 16 + (lane >> 4) * 8;
                uint32_t addr = a_base + (uint32_t)(row * LDA_S + col) * 2u;
                asm volatile("ldmatrix.sync.aligned.m8n8.x4.shared.b16 {%0,%1,%2,%3}, [%4];"
                             : "=r"(a[mt][0]), "=r"(a[mt][1]), "=r"(a[mt][2]), "=r"(a[mt][3])
                             : "r"(addr));
            }
#pragma unroll
            for (int np = 0; np < 2; np++) {
                int row = k16 * 16 + (lane & 15);
                int col = warp_n * 32 + np * 16 + (lane >> 4) * 8;
                uint32_t addr = b_base + (uint32_t)(row * LDB_S + col) * 2u;
                asm volatile("ldmatrix.sync.aligned.m8n8.x4.trans.shared.b16 {%0,%1,%2,%3}, [%4];"
                             : "=r"(b[np * 2][0]), "=r"(b[np * 2][1]),
                               "=r"(b[np * 2 + 1][0]), "=r"(b[np * 2 + 1][1])
                             : "r"(addr));
            }
#pragma unroll
            for (int mt = 0; mt < 2; mt++) {
#pragma unroll
                for (int nt = 0; nt < 4; nt++) {
                    asm volatile(
                        "mma.sync.aligned.m16n8k16.row.col.f32.f16.f16.f32 "
                        "{%0,%1,%2,%3}, {%4,%5,%6,%7}, {%8,%9}, {%0,%1,%2,%3};"
                        : "+f"(acc[mt][nt][0]), "+f"(acc[mt][nt][1]),
                          "+f"(acc[mt][nt][2]), "+f"(acc[mt][nt][3])
                        : "r"(a[mt][0]), "r"(a[mt][1]), "r"(a[mt][2]), "r"(a[mt][3]),
                          "r"(b[nt][0]), "r"(b[nt][1]));
                }
            }
        }
        __syncthreads();
        buf ^= 1;
    }

    // epilogue: add bias, store fp32
    const int row0 = bm * BM + warp_m * 32 + (lane >> 2);
    const int col0 = bn * BN + warp_n * 32 + (lane & 3) * 2;
#pragma unroll
    for (int mt = 0; mt < 2; mt++) {
#pragma unroll
        for (int nt = 0; nt < 4; nt++) {
            int col = col0 + nt * 8;
            float2 bv = *(const float2*)&bias[col];
            int r0 = row0 + mt * 16;
            float2 v0 = {acc[mt][nt][0] + bv.x, acc[mt][nt][1] + bv.y};
            float2 v1 = {acc[mt][nt][2] + bv.x, acc[mt][nt][3] + bv.y};
            *(float2*)&out[(size_t)r0 * N_TOTAL + col] = v0;
            *(float2*)&out[(size_t)(r0 + 8) * N_TOTAL + col] = v1;
        }
    }
}

// ---------------------------------------------------------------------------
extern "C" void kernel_launch(void* const* d_in, const int* in_sizes, int n_in,
                              void* d_out, int out_size) {
    const float* x       = (const float*)d_in[0];
    const int*   qweight = (const int*)d_in[1];
    const int*   qzeros  = (const int*)d_in[2];
    const float* scales  = (const float*)d_in[3];
    const float* bias    = (const float*)d_in[4];
    float*       out     = (float*)d_out;

    cudaFuncSetAttribute(gemm_kernel,
                         cudaFuncAttributeMaxDynamicSharedMemorySize, SMEM_TOTAL);

    prep_kernel<<<CONV_NBLK + DEQ_NBLK, 256>>>(x, qweight, qzeros, scales);
    gemm_kernel<<<dim3(M_TOTAL / BM, N_TOTAL / BN), 256, SMEM_TOTAL>>>(bias, out);
}

// round 14
// speedup vs baseline: 1.0412x; 1.0412x over previous
#include <cuda_runtime.h>
#include <cuda_fp16.h>
#include <cstdint>

#define M_TOTAL 2048
#define K_TOTAL 4096
#define N_TOTAL 11008
#define GROUPSZ 128
#define NPACK   (N_TOTAL / 8)   // 1376

// Scratch (__device__ globals: allocation-free rules)
__device__ __half g_W[(size_t)K_TOTAL * N_TOTAL];   // ~90 MB fp16 dequantized W [K][N]
__device__ __half g_X[(size_t)M_TOTAL * K_TOTAL];   // ~16 MB fp16 activations [M][K]

#define CONV_NBLK 4096                     // M*K/8/256
#define DEQ_NBLK  (K_TOTAL * NPACK / 256)  // 22016

// ---------------------------------------------------------------------------
// Kernel 1 (merged prep): convert x fp32->fp16 + magic-number int4 dequant
// (R11-proven, ~30us)
// ---------------------------------------------------------------------------
__global__ void prep_kernel(const float* __restrict__ x,
                            const int* __restrict__ qweight,
                            const int* __restrict__ qzeros,
                            const float* __restrict__ scales) {
    const int b = blockIdx.x;
    if (b < CONV_NBLK) {
        int idx = b * 256 + threadIdx.x;
        const float4* xv = (const float4*)x;
        float4 f0 = xv[idx * 2 + 0];
        float4 f1 = xv[idx * 2 + 1];
        __half2 h[4];
        h[0] = __floats2half2_rn(f0.x, f0.y);
        h[1] = __floats2half2_rn(f0.z, f0.w);
        h[2] = __floats2half2_rn(f1.x, f1.y);
        h[3] = __floats2half2_rn(f1.z, f1.w);
        *(uint4*)(&g_X[(size_t)idx * 8]) = *(uint4*)h;
    } else {
        int idx = (b - CONV_NBLK) * 256 + threadIdx.x;
        int k  = idx / NPACK;
        int np = idx - k * NPACK;
        int g  = k / GROUPSZ;

        uint32_t qw = ((const uint32_t*)qweight)[idx];
        uint32_t qz = ((const uint32_t*)qzeros)[(size_t)g * NPACK + np];
        const float4* s4 = (const float4*)(scales + (size_t)g * N_TOTAL + np * 8);
        float4 s0 = s4[0];
        float4 s1 = s4[1];
        __half2 sh[4];
        sh[0] = __floats2half2_rn(s0.x, s0.y);
        sh[1] = __floats2half2_rn(s0.z, s0.w);
        sh[2] = __floats2half2_rn(s1.x, s1.y);
        sh[3] = __floats2half2_rn(s1.z, s1.w);

        __half2 r[4];
#pragma unroll
        for (int p = 0; p < 4; p++) {
            uint32_t xw = qw >> (8 * p);
            uint32_t xz = qz >> (8 * p);
            uint32_t tw = 0x64006400u | (xw & 0xFu) | ((xw & 0xF0u) << 12);
            uint32_t tz = 0x64006400u | (xz & 0xFu) | ((xz & 0xF0u) << 12);
            __half2 d = __hsub2(*(__half2*)&tw, *(__half2*)&tz);  // exact ints
            r[p] = __hmul2(d, sh[p]);
        }
        *(uint4*)(&g_W[(size_t)k * N_TOTAL + np * 8]) = *(uint4*)r;
    }
}

// ---------------------------------------------------------------------------
// Kernel 2: GEMM  out[M,N] = X[M,K] * W[K,N] + bias
// mma.sync m16n8k16 fp16->fp32.  BM=128 BN=256 BK=64, 8 warps (2Mx4N),
// warp tile 64x64 (128B smem-read per HMMA — shared pipe decoupled).
// 4-stage cp.async (R11 skeleton, wait_group 2) + FRAGMENT DOUBLE-BUFFER:
// ldsm for k16+1 overlaps the 32-HMMA block of k16.  occ 1, ~220 regs, ILP.
// Grid swizzled (bm fastest).
// ---------------------------------------------------------------------------
#define BM 128
#define BN 256
#define BK 64
#define STAGES 4
#define LDA_S 72            // halves per A row (144B)
#define LDB_S 264           // halves per B row (528B)
#define A_SM_BYTES (BM * LDA_S * 2)            // 18432
#define B_SM_BYTES (BK * LDB_S * 2)            // 33792
#define STAGE_BYTES (A_SM_BYTES + B_SM_BYTES)  // 52224
#define SMEM_TOTAL (STAGES * STAGE_BYTES)      // 208896
#define KT (K_TOTAL / BK)   // 64

__device__ __forceinline__ uint32_t smem_u32(const void* p) {
    return (uint32_t)__cvta_generic_to_shared(p);
}
__device__ __forceinline__ void cp_async_16(uint32_t saddr, const void* gaddr) {
    asm volatile("cp.async.cg.shared.global [%0], [%1], 16;\n" :: "r"(saddr), "l"(gaddr));
}

__global__ void __launch_bounds__(256, 1) gemm_kernel(const float* __restrict__ bias,
                                                      float* __restrict__ out) {
    extern __shared__ char smem[];

    const int tid  = threadIdx.x;
    const int lane = tid & 31;
    const int warp = tid >> 5;
    const int warp_m = warp & 1;   // 0..1 -> 64 rows
    const int warp_n = warp >> 1;  // 0..3 -> 64 cols
    const int bm = blockIdx.x;     // M tile (16) -- fastest
    const int bn = blockIdx.y;     // N tile (43)

    // coalesced global->smem mappings
    const int a_row = tid >> 3;          // 0..31 (+32, 4 iters)
    const int a_c0  = (tid & 7) * 8;     // 128B rows
    const int b_row = tid >> 4;          // 0..15 (+16, 4 iters)
    const int b_c0  = (tid & 15) * 8;    // 2 col-iters x 128 halves

    const __half* gA = g_X + (size_t)(bm * BM) * K_TOTAL;
    const __half* gB = g_W + (size_t)(bn * BN);

    float acc[4][8][4];
#pragma unroll
    for (int i = 0; i < 4; i++)
#pragma unroll
        for (int j = 0; j < 8; j++)
#pragma unroll
            for (int c = 0; c < 4; c++) acc[i][j][c] = 0.f;

#define LOAD_STAGE(st, kq) do {                                                 \
        const int _k0 = (kq) * BK;                                              \
        __half* _As = (__half*)(smem + (st) * STAGE_BYTES);                     \
        __half* _Bs = (__half*)(smem + (st) * STAGE_BYTES + A_SM_BYTES);        \
        _Pragma("unroll")                                                       \
        for (int _i = 0; _i < 4; _i++) {                                        \
            int _r = a_row + _i * 32;                                           \
            cp_async_16(smem_u32(&_As[_r * LDA_S + a_c0]),                      \
                        gA + (size_t)_r * K_TOTAL + _k0 + a_c0);                \
        }                                                                       \
        _Pragma("unroll")                                                       \
        for (int _i = 0; _i < 4; _i++) {                                        \
            int _r = b_row + _i * 16;                                           \
            _Pragma("unroll")                                                   \
            for (int _j = 0; _j < 2; _j++) {                                    \
                int _c = b_c0 + _j * 128;                                       \
                cp_async_16(smem_u32(&_Bs[_r * LDB_S + _c]),                    \
                            gB + (size_t)(_k0 + _r) * N_TOTAL + _c);            \
            }                                                                   \
        }                                                                       \
        asm volatile("cp.async.commit_group;\n" ::);                            \
    } while (0)

    // fragment load for one k16 slice from stage bases
#define FRAG_LOAD(fb, a_base, b_base, k16) do {                                 \
        _Pragma("unroll")                                                       \
        for (int _mt = 0; _mt < 4; _mt++) {                                     \
            int _row = warp_m * 64 + _mt * 16 + (lane & 15);                    \
            int _col = (k16) * 16 + (lane >> 4) * 8;                            \
            uint32_t _ad = (a_base) + (uint32_t)(_row * LDA_S + _col) * 2u;     \
            asm volatile("ldmatrix.sync.aligned.m8n8.x4.shared.b16 "            \
                         "{%0,%1,%2,%3}, [%4];"                                 \
                         : "=r"(af[fb][_mt][0]), "=r"(af[fb][_mt][1]),          \
                           "=r"(af[fb][_mt][2]), "=r"(af[fb][_mt][3])           \
                         : "r"(_ad));                                           \
        }                                                                       \
        _Pragma("unroll")                                                       \
        for (int _nt = 0; _nt < 4; _nt++) {                                     \
            int _row = (k16) * 16 + (lane & 15);                                \
            int _col = warp_n * 64 + _nt * 16 + (lane >> 4) * 8;                \
            uint32_t _ad = (b_base) + (uint32_t)(_row * LDB_S + _col) * 2u;     \
            asm volatile("ldmatrix.sync.aligned.m8n8.x4.trans.shared.b16 "      \
                         "{%0,%1,%2,%3}, [%4];"                                 \
                         : "=r"(bf[fb][_nt * 2][0]), "=r"(bf[fb][_nt * 2][1]),  \
                           "=r"(bf[fb][_nt * 2 + 1][0]),                        \
                           "=r"(bf[fb][_nt * 2 + 1][1])                         \
                         : "r"(_ad));                                           \
        }                                                                       \
    } while (0)

    // prologue: 3 stages in flight
    LOAD_STAGE(0, 0);
    LOAD_STAGE(1, 1);
    LOAD_STAGE(2, 2);

    uint32_t af[2][4][4];
    uint32_t bf[2][8][2];

    int sc = 0;   // compute stage
    int sl = 3;   // next load stage
    for (int kt = 0; kt < KT; kt++) {
        asm volatile("cp.async.wait_group 2;\n" ::);   // stage kt ready
        __syncthreads();                               // stage sl free

        {
            const int knext = (kt + 3 < KT) ? (kt + 3) : kt;  // tail: dead fill
            LOAD_STAGE(sl, knext);
        }

        const uint32_t a_base = smem_u32(smem + sc * STAGE_BYTES);
        const uint32_t b_base = smem_u32(smem + sc * STAGE_BYTES + A_SM_BYTES);

        FRAG_LOAD(0, a_base, b_base, 0);
#pragma unroll
        for (int k16 = 0; k16 < 4; k16++) {
            const int cur = k16 & 1;
            if (k16 < 3) {
                FRAG_LOAD(cur ^ 1, a_base, b_base, k16 + 1);
            }
#pragma unroll
            for (int mt = 0; mt < 4; mt++) {
#pragma unroll
                for (int nt = 0; nt < 8; nt++) {
                    asm volatile(
                        "mma.sync.aligned.m16n8k16.row.col.f32.f16.f16.f32 "
                        "{%0,%1,%2,%3}, {%4,%5,%6,%7}, {%8,%9}, {%0,%1,%2,%3};"
                        : "+f"(acc[mt][nt][0]), "+f"(acc[mt][nt][1]),
                          "+f"(acc[mt][nt][2]), "+f"(acc[mt][nt][3])
                        : "r"(af[cur][mt][0]), "r"(af[cur][mt][1]),
                          "r"(af[cur][mt][2]), "r"(af[cur][mt][3]),
                          "r"(bf[cur][nt][0]), "r"(bf[cur][nt][1]));
                }
            }
        }
        sc = (sc + 1 == STAGES) ? 0 : sc + 1;
        sl = (sl + 1 == STAGES) ? 0 : sl + 1;
    }

    // drain outstanding cp.async before smem goes dead
    asm volatile("cp.async.wait_group 0;\n" ::);
    __syncthreads();

    // epilogue: add bias, store fp32 (R5-verified 64x64 mapping)
    const int row0 = bm * BM + warp_m * 64 + (lane >> 2);
    const int col0 = bn * BN + warp_n * 64 + (lane & 3) * 2;
#pragma unroll
    for (int mt = 0; mt < 4; mt++) {
#pragma unroll
        for (int nt = 0; nt < 8; nt++) {
            int col = col0 + nt * 8;
            float2 bv = *(const float2*)&bias[col];
            int r0 = row0 + mt * 16;
            float2 v0 = {acc[mt][nt][0] + bv.x, acc[mt][nt][1] + bv.y};
            float2 v1 = {acc[mt][nt][2] + bv.x, acc[mt][nt][3] + bv.y};
            *(float2*)&out[(size_t)r0 * N_TOTAL + col] = v0;
            *(float2*)&out[(size_t)(r0 + 8) * N_TOTAL + col] = v1;
        }
    }
}

// ---------------------------------------------------------------------------
extern "C" void kernel_launch(void* const* d_in, const int* in_sizes, int n_in,
                              void* d_out, int out_size) {
    const float* x       = (const float*)d_in[0];
    const int*   qweight = (const int*)d_in[1];
    const int*   qzeros  = (const int*)d_in[2];
    const float* scales  = (const float*)d_in[3];
    const float* bias    = (const float*)d_in[4];
    float*       out     = (float*)d_out;

    cudaFuncSetAttribute(gemm_kernel,
                         cudaFuncAttributeMaxDynamicSharedMemorySize, SMEM_TOTAL);

    prep_kernel<<<CONV_NBLK + DEQ_NBLK, 256>>>(x, qweight, qzeros, scales);
    gemm_kernel<<<dim3(M_TOTAL / BM, N_TOTAL / BN), 256, SMEM_TOTAL>>>(bias, out);
}